// round 1
// baseline (speedup 1.0000x reference)
#include <cuda_runtime.h>
#include <math.h>

#define NV 20000
#define NF 40000
#define EE 320000
#define GG 64
#define D  256
#define D2 512

// ---------------- scratch (device globals; no allocation allowed) ----------
__device__ float g_bufF1[NF * D];   // Fh / tmp / T roles
__device__ float g_bufF2[NF * D];   // aggr_f
__device__ float g_bufV1[NV * D];   // Vh / tmpv
__device__ float g_bufV2[NV * D];   // aggr_v
__device__ float g_gate[NF];
__device__ float g_gagg[GG * D];

// ---------------- GEMM: C[M x 256] = A[M x 256] @ W[256 x 256] (+epilogue) --
// BM=BN=128, BK=8, 256 threads, 8x8 per-thread microtile.
enum { EP_NONE = 0, EP_BIAS = 1, EP_COMBINE = 2, EP_COMBINE_RES = 3 };

template <int MODE>
__global__ __launch_bounds__(256)
void gemm256(const float* __restrict__ A, const float* __restrict__ W,
             const float* __restrict__ Cin, float* __restrict__ Cout,
             const float* __restrict__ bias, const float* __restrict__ res,
             int M)
{
    __shared__ float As[8][128];
    __shared__ float Bs[8][128];

    const int tid = threadIdx.x;
    const int rowBase = blockIdx.y * 128;
    const int colBase = blockIdx.x * 128;

    // A tile load map: 128 rows x 8 k, float4 along K
    const int aRow = tid >> 1;
    const int aK   = (tid & 1) * 4;
    // W tile load map: 8 k x 128 n, float4 along N
    const int bK = tid >> 5;
    const int bN = (tid & 31) * 4;

    const int tx = tid & 15;
    const int ty = tid >> 4;

    float acc[8][8];
#pragma unroll
    for (int i = 0; i < 8; i++)
#pragma unroll
        for (int j = 0; j < 8; j++) acc[i][j] = 0.f;

    for (int k0 = 0; k0 < D; k0 += 8) {
        float4 av;
        const int gr = rowBase + aRow;
        if (gr < M) av = *reinterpret_cast<const float4*>(&A[(size_t)gr * D + k0 + aK]);
        else        av = make_float4(0.f, 0.f, 0.f, 0.f);
        As[aK + 0][aRow] = av.x;
        As[aK + 1][aRow] = av.y;
        As[aK + 2][aRow] = av.z;
        As[aK + 3][aRow] = av.w;

        const float4 bv = *reinterpret_cast<const float4*>(&W[(size_t)(k0 + bK) * D + colBase + bN]);
        *reinterpret_cast<float4*>(&Bs[bK][bN]) = bv;
        __syncthreads();

#pragma unroll
        for (int kk = 0; kk < 8; kk++) {
            float ar[8], br[8];
#pragma unroll
            for (int i = 0; i < 8; i++) ar[i] = As[kk][ty * 8 + i];
#pragma unroll
            for (int j = 0; j < 8; j++) br[j] = Bs[kk][tx * 8 + j];
#pragma unroll
            for (int i = 0; i < 8; i++)
#pragma unroll
                for (int j = 0; j < 8; j++) acc[i][j] += ar[i] * br[j];
        }
        __syncthreads();
    }

#pragma unroll
    for (int i = 0; i < 8; i++) {
        const int r = rowBase + ty * 8 + i;
        if (r >= M) break;
#pragma unroll
        for (int j = 0; j < 8; j += 4) {
            const int c = colBase + tx * 8 + j;
            float4 v = make_float4(acc[i][j], acc[i][j + 1], acc[i][j + 2], acc[i][j + 3]);
            if (MODE == EP_BIAS) {
                v.x += bias[c + 0]; v.y += bias[c + 1];
                v.z += bias[c + 2]; v.w += bias[c + 3];
            } else if (MODE == EP_COMBINE || MODE == EP_COMBINE_RES) {
                const float4 ci = *reinterpret_cast<const float4*>(&Cin[(size_t)r * D + c]);
                v.x = fmaxf(v.x + ci.x + bias[c + 0], 0.f);
                v.y = fmaxf(v.y + ci.y + bias[c + 1], 0.f);
                v.z = fmaxf(v.z + ci.z + bias[c + 2], 0.f);
                v.w = fmaxf(v.w + ci.w + bias[c + 3], 0.f);
                if (MODE == EP_COMBINE_RES) {
                    const float4 rr = *reinterpret_cast<const float4*>(&res[(size_t)r * D + c]);
                    v.x += rr.x; v.y += rr.y; v.z += rr.z; v.w += rr.w;
                }
            }
            *reinterpret_cast<float4*>(&Cout[(size_t)r * D + c]) = v;
        }
    }
}

// ---------------- per-edge message + scatter-add --------------------------
// msg = relu(TA[idxA[e]] + TB[idxB[e]] + bias); atomicAdd into out[idxA[e]].
__global__ __launch_bounds__(256)
void edge_msg(const float* __restrict__ TA, const int* __restrict__ idxA,
              const float* __restrict__ TB, const int* __restrict__ idxB,
              const float* __restrict__ bias, float* __restrict__ out)
{
    const int e = blockIdx.x * 4 + threadIdx.y;
    if (e >= EE) return;
    const int ia = __ldg(&idxA[e]);
    const int ib = __ldg(&idxB[e]);
    const int d  = threadIdx.x * 4;

    const float4 a  = *reinterpret_cast<const float4*>(&TA[(size_t)ia * D + d]);
    const float4 b  = *reinterpret_cast<const float4*>(&TB[(size_t)ib * D + d]);
    const float4 bb = *reinterpret_cast<const float4*>(&bias[d]);

    const float m0 = fmaxf(a.x + b.x + bb.x, 0.f);
    const float m1 = fmaxf(a.y + b.y + bb.y, 0.f);
    const float m2 = fmaxf(a.z + b.z + bb.z, 0.f);
    const float m3 = fmaxf(a.w + b.w + bb.w, 0.f);

    float* o = &out[(size_t)ia * D + d];
    atomicAdd(o + 0, m0);
    atomicAdd(o + 1, m1);
    atomicAdd(o + 2, m2);
    atomicAdd(o + 3, m3);
}

// ---------------- attention pooling ---------------------------------------
__global__ __launch_bounds__(256)
void gate_kernel(const float* __restrict__ F, const float* __restrict__ gW,
                 const float* __restrict__ gb, float* __restrict__ gate)
{
    const int w = threadIdx.x >> 5, lane = threadIdx.x & 31;
    const int row = blockIdx.x * 8 + w;
    if (row >= NF) return;
    float s = 0.f;
#pragma unroll
    for (int i = 0; i < 8; i++) {
        const int k = lane + i * 32;
        s += F[(size_t)row * D + k] * __ldg(&gW[k]);
    }
#pragma unroll
    for (int o = 16; o > 0; o >>= 1) s += __shfl_xor_sync(0xffffffff, s, o);
    if (lane == 0) gate[row] = s + gb[0];
}

__device__ __forceinline__ int lbound(const int* __restrict__ a, int n, int v)
{
    int lo = 0, hi = n;
    while (lo < hi) {
        int mid = (lo + hi) >> 1;
        if (a[mid] < v) lo = mid + 1; else hi = mid;
    }
    return lo;
}

// one block per graph: segment softmax over gate + weighted sum of T rows
__global__ __launch_bounds__(256)
void graph_agg(const float* __restrict__ gate, const float* __restrict__ T,
               const int* __restrict__ batch, float* __restrict__ gagg)
{
    __shared__ float red[256];
    __shared__ int sse[2];
    const int g = blockIdx.x, tid = threadIdx.x;
    if (tid == 0) sse[0] = lbound(batch, NF, g);
    if (tid == 1) sse[1] = lbound(batch, NF, g + 1);
    __syncthreads();
    const int s = sse[0], e = sse[1];

    float m = -INFINITY;
    for (int i = s + tid; i < e; i += 256) m = fmaxf(m, __ldg(&gate[i]));
    red[tid] = m; __syncthreads();
    for (int o = 128; o > 0; o >>= 1) {
        if (tid < o) red[tid] = fmaxf(red[tid], red[tid + o]);
        __syncthreads();
    }
    const float mm = red[0]; __syncthreads();

    float sum = 0.f;
    for (int i = s + tid; i < e; i += 256) sum += expf(__ldg(&gate[i]) - mm);
    red[tid] = sum; __syncthreads();
    for (int o = 128; o > 0; o >>= 1) {
        if (tid < o) red[tid] += red[tid + o];
        __syncthreads();
    }
    const float inv = (e > s) ? 1.f / red[0] : 0.f;

    float acc = 0.f;
    for (int i = s; i < e; i++) {
        const float alpha = expf(__ldg(&gate[i]) - mm) * inv;
        acc += alpha * T[(size_t)i * D + tid];
    }
    gagg[g * D + tid] = acc;
}

// g = relu(gagg @ glW_top + glb)   (g_prev = 0, bottom half multiplies zeros)
__global__ __launch_bounds__(256)
void final_g(const float* __restrict__ gagg, const float* __restrict__ glW,
             const float* __restrict__ glb, float* __restrict__ out)
{
    __shared__ float row[D];
    const int g = blockIdx.x, c = threadIdx.x;
    row[c] = gagg[g * D + c];
    __syncthreads();
    float s = glb[c];
#pragma unroll 8
    for (int k = 0; k < D; k++) s += row[k] * glW[(size_t)k * D + c];
    out[(size_t)g * D + c] = fmaxf(s, 0.f);
}

// ---------------------------------------------------------------------------
extern "C" void kernel_launch(void* const* d_in, const int* in_sizes, int n_in,
                              void* d_out, int out_size)
{
    const float* variables = (const float*)d_in[0];
    const float* factors   = (const float*)d_in[1];
    // d_in[2] = edge_attr (unused by the math)
    const int* edge_index  = (const int*)d_in[3];
    const int* batch       = (const int*)d_in[4];
    const float* mW_v2f = (const float*)d_in[5];
    const float* mb_v2f = (const float*)d_in[6];
    const float* cW_v2f = (const float*)d_in[7];
    const float* cb_v2f = (const float*)d_in[8];
    const float* mW_f2v = (const float*)d_in[9];
    const float* mb_f2v = (const float*)d_in[10];
    const float* cW_f2v = (const float*)d_in[11];
    const float* cb_f2v = (const float*)d_in[12];
    const float* gate_W = (const float*)d_in[13];
    const float* gate_b = (const float*)d_in[14];
    const float* att_W  = (const float*)d_in[15];
    const float* att_b  = (const float*)d_in[16];
    const float* gl_W   = (const float*)d_in[17];
    const float* gl_b   = (const float*)d_in[18];

    const int* src = edge_index;        // row 0: variable idx
    const int* dst = edge_index + EE;   // row 1: factor idx

    float* outV = (float*)d_out;
    float* outF = outV + (size_t)NV * D;
    float* outG = outF + (size_t)NF * D;

    float *bufF1, *bufF2, *bufV1, *bufV2, *gate, *gagg;
    cudaGetSymbolAddress((void**)&bufF1, g_bufF1);
    cudaGetSymbolAddress((void**)&bufF2, g_bufF2);
    cudaGetSymbolAddress((void**)&bufV1, g_bufV1);
    cudaGetSymbolAddress((void**)&bufV2, g_bufV2);
    cudaGetSymbolAddress((void**)&gate,  g_gate);
    cudaGetSymbolAddress((void**)&gagg,  g_gagg);

    // working copies live directly in d_out
    cudaMemcpyAsync(outV, variables, (size_t)NV * D * sizeof(float),
                    cudaMemcpyDeviceToDevice, 0);
    cudaMemcpyAsync(outF, factors, (size_t)NF * D * sizeof(float),
                    cudaMemcpyDeviceToDevice, 0);

    const dim3 gemmBlk(256);
    const dim3 gridF(2, (NF + 127) / 128);
    const dim3 gridV(2, (NV + 127) / 128);
    const dim3 edgeBlk(64, 4);
    const int edgeGrid = (EE + 3) / 4;

    for (int l = 0; l < 2; l++) {
        // ---- variable -> factor ----
        {
            const float* mW = mW_v2f + (size_t)l * D2 * D;
            const float* mb = mb_v2f + (size_t)l * D;
            const float* cW = cW_v2f + (size_t)l * D2 * D;
            const float* cb = cb_v2f + (size_t)l * D;

            gemm256<EP_NONE><<<gridF, gemmBlk>>>(outF, mW,          nullptr, bufF1, nullptr, nullptr, NF);
            gemm256<EP_NONE><<<gridV, gemmBlk>>>(outV, mW + D * D,  nullptr, bufV1, nullptr, nullptr, NV);
            cudaMemsetAsync(bufF2, 0, (size_t)NF * D * sizeof(float), 0);
            edge_msg<<<edgeGrid, edgeBlk>>>(bufF1, dst, bufV1, src, mb, bufF2);
            gemm256<EP_NONE><<<gridF, gemmBlk>>>(outF, cW, nullptr, bufF1, nullptr, nullptr, NF);     // tmp = F@cWt
            gemm256<EP_COMBINE><<<gridF, gemmBlk>>>(bufF2, cW + D * D, bufF1, outF, cb, nullptr, NF); // F = relu(tmp + aggr@cWb + cb)
        }
        // ---- factor -> variable ----
        {
            const float* mW = mW_f2v + (size_t)l * D2 * D;
            const float* mb = mb_f2v + (size_t)l * D;
            const float* cW = cW_f2v + (size_t)l * D2 * D;
            const float* cb = cb_f2v + (size_t)l * D;

            gemm256<EP_NONE><<<gridV, gemmBlk>>>(outV, mW,          nullptr, bufV1, nullptr, nullptr, NV);
            gemm256<EP_NONE><<<gridF, gemmBlk>>>(outF, mW + D * D,  nullptr, bufF1, nullptr, nullptr, NF);
            cudaMemsetAsync(bufV2, 0, (size_t)NV * D * sizeof(float), 0);
            edge_msg<<<edgeGrid, edgeBlk>>>(bufV1, src, bufF1, dst, mb, bufV2);
            gemm256<EP_NONE><<<gridV, gemmBlk>>>(outV, cW, nullptr, bufV1, nullptr, nullptr, NV);         // tmpv = V@cWt
            gemm256<EP_COMBINE_RES><<<gridV, gemmBlk>>>(bufV2, cW + D * D, bufV1, outV, cb, outV, NV);    // V += relu(...)
        }
    }

    // ---- GlobalNode attention pooling ----
    gate_kernel<<<(NF + 7) / 8, 256>>>(outF, gate_W, gate_b, gate);
    gemm256<EP_BIAS><<<gridF, gemmBlk>>>(outF, att_W, nullptr, bufF1, att_b, nullptr, NF);  // T = F@attW + attb
    graph_agg<<<GG, 256>>>(gate, bufF1, batch, gagg);
    final_g<<<GG, 256>>>(gagg, gl_W, gl_b, outG);
}

// round 2
// speedup vs baseline: 2.3255x; 2.3255x over previous
#include <cuda_runtime.h>
#include <math.h>

#define NV 20000
#define NF 40000
#define EE 320000
#define GG 64
#define D  256
#define D2 512

// ---------------- scratch (device globals; no allocation allowed) ----------
__device__ float g_bufF1[NF * D];
__device__ float g_bufF2[NF * D];
__device__ float g_bufV1[NV * D];
__device__ float g_bufV2[NV * D];
__device__ float g_gate[NF];
__device__ float g_gagg[GG * D];

enum { EP_NONE = 0, EP_BIAS = 1, EP_COMBINE = 2, EP_COMBINE_RES = 3 };

__device__ __forceinline__ unsigned f2tf(float f) {
    unsigned r;
    asm("cvt.rna.tf32.f32 %0, %1;" : "=r"(r) : "f"(f));
    return r;
}

__device__ __forceinline__ void mma_tf32(float* d, const unsigned* a,
                                         const unsigned* b, const float* c) {
    asm volatile(
        "mma.sync.aligned.m16n8k8.row.col.f32.tf32.tf32.f32 "
        "{%0,%1,%2,%3}, {%4,%5,%6,%7}, {%8,%9}, {%10,%11,%12,%13};"
        : "=f"(d[0]), "=f"(d[1]), "=f"(d[2]), "=f"(d[3])
        : "r"(a[0]), "r"(a[1]), "r"(a[2]), "r"(a[3]),
          "r"(b[0]), "r"(b[1]),
          "f"(c[0]), "f"(c[1]), "f"(c[2]), "f"(c[3]));
}

// ---------------- GEMM: C[M x 256] = A[M x 256] @ W[256 x 256] (+epilogue) --
// Tensor-core TF32 path: 128x128x16 tile, 8 warps, 64x32 per warp.
template <int MODE>
__global__ __launch_bounds__(256)
void gemm_tc(const float* __restrict__ A, const float* __restrict__ W,
             const float* __restrict__ Cin, float* __restrict__ Cout,
             const float* __restrict__ bias, const float* __restrict__ res,
             int M)
{
    __shared__ unsigned As[128][20];   // [row][k], pad 20 -> conflict-free frag reads
    __shared__ unsigned Bs[16][136];   // [k][n],  pad 136 -> conflict-free frag reads

    const int tid  = threadIdx.x;
    const int wid  = tid >> 5;
    const int lane = tid & 31;
    const int g = lane >> 2;      // group id (0..7)
    const int c = lane & 3;       // thread-in-group (0..3)

    const int rowBase = blockIdx.y * 128;
    const int colBase = blockIdx.x * 128;
    const int wr = (wid & 1) * 64;   // warp row offset in tile
    const int wc = (wid >> 1) * 32;  // warp col offset in tile

    float acc[4][4][4];
#pragma unroll
    for (int i = 0; i < 4; i++)
#pragma unroll
        for (int j = 0; j < 4; j++)
#pragma unroll
            for (int k = 0; k < 4; k++) acc[i][j][k] = 0.f;

    for (int k0 = 0; k0 < D; k0 += 16) {
        // A tile: 128 rows x 16 k  (512 float4 slots, 2 per thread)
#pragma unroll
        for (int i = 0; i < 2; i++) {
            const int s = tid + i * 256;
            const int r = s >> 2;
            const int kk = (s & 3) * 4;
            float4 v = make_float4(0.f, 0.f, 0.f, 0.f);
            const int gr = rowBase + r;
            if (gr < M) v = *reinterpret_cast<const float4*>(&A[(size_t)gr * D + k0 + kk]);
            As[r][kk + 0] = f2tf(v.x);
            As[r][kk + 1] = f2tf(v.y);
            As[r][kk + 2] = f2tf(v.z);
            As[r][kk + 3] = f2tf(v.w);
        }
        // B tile: 16 k x 128 n
#pragma unroll
        for (int i = 0; i < 2; i++) {
            const int s = tid + i * 256;
            const int kk = s >> 5;
            const int n4 = (s & 31) * 4;
            const float4 v = *reinterpret_cast<const float4*>(&W[(size_t)(k0 + kk) * D + colBase + n4]);
            Bs[kk][n4 + 0] = f2tf(v.x);
            Bs[kk][n4 + 1] = f2tf(v.y);
            Bs[kk][n4 + 2] = f2tf(v.z);
            Bs[kk][n4 + 3] = f2tf(v.w);
        }
        __syncthreads();

#pragma unroll
        for (int ks = 0; ks < 16; ks += 8) {
            unsigned a[4][4], b[4][2];
#pragma unroll
            for (int mf = 0; mf < 4; mf++) {
                const int mrow = wr + mf * 16;
                a[mf][0] = As[mrow + g    ][ks + c    ];
                a[mf][1] = As[mrow + g + 8][ks + c    ];
                a[mf][2] = As[mrow + g    ][ks + c + 4];
                a[mf][3] = As[mrow + g + 8][ks + c + 4];
            }
#pragma unroll
            for (int nf = 0; nf < 4; nf++) {
                const int ncol = wc + nf * 8;
                b[nf][0] = Bs[ks + c    ][ncol + g];
                b[nf][1] = Bs[ks + c + 4][ncol + g];
            }
#pragma unroll
            for (int mf = 0; mf < 4; mf++)
#pragma unroll
                for (int nf = 0; nf < 4; nf++)
                    mma_tf32(acc[mf][nf], a[mf], b[nf], acc[mf][nf]);
        }
        __syncthreads();
    }

    // epilogue: rows wr+mf*16+g(+8), cols wc+nf*8+2c(+1)
#pragma unroll
    for (int mf = 0; mf < 4; mf++) {
#pragma unroll
        for (int half = 0; half < 2; half++) {
            const int r = rowBase + wr + mf * 16 + g + half * 8;
            if (r >= M) continue;
#pragma unroll
            for (int nf = 0; nf < 4; nf++) {
                const int col = colBase + wc + nf * 8 + 2 * c;
                float2 v = make_float2(acc[mf][nf][half * 2], acc[mf][nf][half * 2 + 1]);
                if (MODE == EP_BIAS) {
                    v.x += bias[col + 0];
                    v.y += bias[col + 1];
                } else if (MODE == EP_COMBINE || MODE == EP_COMBINE_RES) {
                    const float2 ci = *reinterpret_cast<const float2*>(&Cin[(size_t)r * D + col]);
                    v.x = fmaxf(v.x + ci.x + bias[col + 0], 0.f);
                    v.y = fmaxf(v.y + ci.y + bias[col + 1], 0.f);
                    if (MODE == EP_COMBINE_RES) {
                        const float2 rr = *reinterpret_cast<const float2*>(&res[(size_t)r * D + col]);
                        v.x += rr.x; v.y += rr.y;
                    }
                }
                *reinterpret_cast<float2*>(&Cout[(size_t)r * D + col]) = v;
            }
        }
    }
}

// ---------------- per-edge message + scatter-add --------------------------
// msg = relu(TA[idxA[e]] + TB[idxB[e]] + bias); red.add into out[idxA[e]].
__global__ __launch_bounds__(256)
void edge_msg(const float* __restrict__ TA, const int* __restrict__ idxA,
              const float* __restrict__ TB, const int* __restrict__ idxB,
              const float* __restrict__ bias, float* __restrict__ out)
{
    const int e = blockIdx.x * 4 + threadIdx.y;
    if (e >= EE) return;
    const int ia = __ldg(&idxA[e]);
    const int ib = __ldg(&idxB[e]);
    const int d  = threadIdx.x * 4;

    const float4 a  = *reinterpret_cast<const float4*>(&TA[(size_t)ia * D + d]);
    const float4 b  = *reinterpret_cast<const float4*>(&TB[(size_t)ib * D + d]);
    const float4 bb = *reinterpret_cast<const float4*>(&bias[d]);

    const float m0 = fmaxf(a.x + b.x + bb.x, 0.f);
    const float m1 = fmaxf(a.y + b.y + bb.y, 0.f);
    const float m2 = fmaxf(a.z + b.z + bb.z, 0.f);
    const float m3 = fmaxf(a.w + b.w + bb.w, 0.f);

    float* o = &out[(size_t)ia * D + d];
    asm volatile("red.global.add.v4.f32 [%0], {%1,%2,%3,%4};"
                 :: "l"(o), "f"(m0), "f"(m1), "f"(m2), "f"(m3) : "memory");
}

// ---------------- attention pooling ---------------------------------------
__global__ __launch_bounds__(256)
void gate_kernel(const float* __restrict__ F, const float* __restrict__ gW,
                 const float* __restrict__ gb, float* __restrict__ gate)
{
    const int w = threadIdx.x >> 5, lane = threadIdx.x & 31;
    const int row = blockIdx.x * 8 + w;
    if (row >= NF) return;
    float s = 0.f;
#pragma unroll
    for (int i = 0; i < 8; i++) {
        const int k = lane + i * 32;
        s += F[(size_t)row * D + k] * __ldg(&gW[k]);
    }
#pragma unroll
    for (int o = 16; o > 0; o >>= 1) s += __shfl_xor_sync(0xffffffff, s, o);
    if (lane == 0) gate[row] = s + gb[0];
}

__device__ __forceinline__ int lbound(const int* __restrict__ a, int n, int v)
{
    int lo = 0, hi = n;
    while (lo < hi) {
        int mid = (lo + hi) >> 1;
        if (a[mid] < v) lo = mid + 1; else hi = mid;
    }
    return lo;
}

__global__ __launch_bounds__(256)
void graph_agg(const float* __restrict__ gate, const float* __restrict__ T,
               const int* __restrict__ batch, float* __restrict__ gagg)
{
    __shared__ float red[256];
    __shared__ int sse[2];
    const int g = blockIdx.x, tid = threadIdx.x;
    if (tid == 0) sse[0] = lbound(batch, NF, g);
    if (tid == 1) sse[1] = lbound(batch, NF, g + 1);
    __syncthreads();
    const int s = sse[0], e = sse[1];

    float m = -INFINITY;
    for (int i = s + tid; i < e; i += 256) m = fmaxf(m, __ldg(&gate[i]));
    red[tid] = m; __syncthreads();
    for (int o = 128; o > 0; o >>= 1) {
        if (tid < o) red[tid] = fmaxf(red[tid], red[tid + o]);
        __syncthreads();
    }
    const float mm = red[0]; __syncthreads();

    float sum = 0.f;
    for (int i = s + tid; i < e; i += 256) sum += expf(__ldg(&gate[i]) - mm);
    red[tid] = sum; __syncthreads();
    for (int o = 128; o > 0; o >>= 1) {
        if (tid < o) red[tid] += red[tid + o];
        __syncthreads();
    }
    const float inv = (e > s) ? 1.f / red[0] : 0.f;

    float acc = 0.f;
    for (int i = s; i < e; i++) {
        const float alpha = expf(__ldg(&gate[i]) - mm) * inv;
        acc += alpha * T[(size_t)i * D + tid];
    }
    gagg[g * D + tid] = acc;
}

__global__ __launch_bounds__(256)
void final_g(const float* __restrict__ gagg, const float* __restrict__ glW,
             const float* __restrict__ glb, float* __restrict__ out)
{
    __shared__ float row[D];
    const int g = blockIdx.x, c = threadIdx.x;
    row[c] = gagg[g * D + c];
    __syncthreads();
    float s = glb[c];
#pragma unroll 8
    for (int k = 0; k < D; k++) s += row[k] * glW[(size_t)k * D + c];
    out[(size_t)g * D + c] = fmaxf(s, 0.f);
}

// ---------------------------------------------------------------------------
extern "C" void kernel_launch(void* const* d_in, const int* in_sizes, int n_in,
                              void* d_out, int out_size)
{
    const float* variables = (const float*)d_in[0];
    const float* factors   = (const float*)d_in[1];
    // d_in[2] = edge_attr (unused by the math)
    const int* edge_index  = (const int*)d_in[3];
    const int* batch       = (const int*)d_in[4];
    const float* mW_v2f = (const float*)d_in[5];
    const float* mb_v2f = (const float*)d_in[6];
    const float* cW_v2f = (const float*)d_in[7];
    const float* cb_v2f = (const float*)d_in[8];
    const float* mW_f2v = (const float*)d_in[9];
    const float* mb_f2v = (const float*)d_in[10];
    const float* cW_f2v = (const float*)d_in[11];
    const float* cb_f2v = (const float*)d_in[12];
    const float* gate_W = (const float*)d_in[13];
    const float* gate_b = (const float*)d_in[14];
    const float* att_W  = (const float*)d_in[15];
    const float* att_b  = (const float*)d_in[16];
    const float* gl_W   = (const float*)d_in[17];
    const float* gl_b   = (const float*)d_in[18];

    const int* src = edge_index;        // row 0: variable idx
    const int* dst = edge_index + EE;   // row 1: factor idx

    float* outV = (float*)d_out;
    float* outF = outV + (size_t)NV * D;
    float* outG = outF + (size_t)NF * D;

    float *bufF1, *bufF2, *bufV1, *bufV2, *gate, *gagg;
    cudaGetSymbolAddress((void**)&bufF1, g_bufF1);
    cudaGetSymbolAddress((void**)&bufF2, g_bufF2);
    cudaGetSymbolAddress((void**)&bufV1, g_bufV1);
    cudaGetSymbolAddress((void**)&bufV2, g_bufV2);
    cudaGetSymbolAddress((void**)&gate,  g_gate);
    cudaGetSymbolAddress((void**)&gagg,  g_gagg);

    cudaMemcpyAsync(outV, variables, (size_t)NV * D * sizeof(float),
                    cudaMemcpyDeviceToDevice, 0);
    cudaMemcpyAsync(outF, factors, (size_t)NF * D * sizeof(float),
                    cudaMemcpyDeviceToDevice, 0);

    const dim3 gemmBlk(256);
    const dim3 gridF(2, (NF + 127) / 128);
    const dim3 gridV(2, (NV + 127) / 128);
    const dim3 edgeBlk(64, 4);
    const int edgeGrid = (EE + 3) / 4;

    for (int l = 0; l < 2; l++) {
        // ---- variable -> factor ----
        {
            const float* mW = mW_v2f + (size_t)l * D2 * D;
            const float* mb = mb_v2f + (size_t)l * D;
            const float* cW = cW_v2f + (size_t)l * D2 * D;
            const float* cb = cb_v2f + (size_t)l * D;

            gemm_tc<EP_NONE><<<gridF, gemmBlk>>>(outF, mW,         nullptr, bufF1, nullptr, nullptr, NF);
            gemm_tc<EP_NONE><<<gridV, gemmBlk>>>(outV, mW + D * D, nullptr, bufV1, nullptr, nullptr, NV);
            cudaMemsetAsync(bufF2, 0, (size_t)NF * D * sizeof(float), 0);
            edge_msg<<<edgeGrid, edgeBlk>>>(bufF1, dst, bufV1, src, mb, bufF2);
            gemm_tc<EP_NONE><<<gridF, gemmBlk>>>(outF, cW, nullptr, bufF1, nullptr, nullptr, NF);
            gemm_tc<EP_COMBINE><<<gridF, gemmBlk>>>(bufF2, cW + D * D, bufF1, outF, cb, nullptr, NF);
        }
        // ---- factor -> variable ----
        {
            const float* mW = mW_f2v + (size_t)l * D2 * D;
            const float* mb = mb_f2v + (size_t)l * D;
            const float* cW = cW_f2v + (size_t)l * D2 * D;
            const float* cb = cb_f2v + (size_t)l * D;

            gemm_tc<EP_NONE><<<gridV, gemmBlk>>>(outV, mW,         nullptr, bufV1, nullptr, nullptr, NV);
            gemm_tc<EP_NONE><<<gridF, gemmBlk>>>(outF, mW + D * D, nullptr, bufF1, nullptr, nullptr, NF);
            cudaMemsetAsync(bufV2, 0, (size_t)NV * D * sizeof(float), 0);
            edge_msg<<<edgeGrid, edgeBlk>>>(bufV1, src, bufF1, dst, mb, bufV2);
            gemm_tc<EP_NONE><<<gridV, gemmBlk>>>(outV, cW, nullptr, bufV1, nullptr, nullptr, NV);
            gemm_tc<EP_COMBINE_RES><<<gridV, gemmBlk>>>(bufV2, cW + D * D, bufV1, outV, cb, outV, NV);
        }
    }

    // ---- GlobalNode attention pooling ----
    gate_kernel<<<(NF + 7) / 8, 256>>>(outF, gate_W, gate_b, gate);
    gemm_tc<EP_BIAS><<<gridF, gemmBlk>>>(outF, att_W, nullptr, bufF1, att_b, nullptr, NF);
    graph_agg<<<GG, 256>>>(gate, bufF1, batch, gagg);
    final_g<<<GG, 256>>>(gagg, gl_W, gl_b, outG);
}

// round 3
// speedup vs baseline: 3.2463x; 1.3959x over previous
#include <cuda_runtime.h>
#include <math.h>

#define NV 20000
#define NF 40000
#define EE 320000
#define GG 64
#define D  256
#define D2 512

// ---------------- scratch (device globals; no allocation allowed) ----------
__device__ float g_bufF1[NF * D];
__device__ float g_bufF2[NF * D];
__device__ float g_bufV1[NV * D];
__device__ float g_bufV2[NV * D];
__device__ float g_gate[NF];
__device__ float g_gagg[GG * D];
// CSR scratch
__device__ int g_cntF[NF], g_cntV[NV];
__device__ int g_offF[NF + 1], g_offV[NV + 1];
__device__ int g_curF[NF], g_curV[NV];
__device__ int g_elF[EE], g_elV[EE];

enum { EP_NONE = 0, EP_BIAS = 1, EP_RELU_BIAS = 2, EP_RELU_BIAS_RES = 3 };

__device__ __forceinline__ unsigned f2tf(float f) {
    unsigned r;
    asm("cvt.rna.tf32.f32 %0, %1;" : "=r"(r) : "f"(f));
    return r;
}

__device__ __forceinline__ void mma_tf32(float* d, const unsigned* a,
                                         const unsigned* b, const float* c) {
    asm volatile(
        "mma.sync.aligned.m16n8k8.row.col.f32.tf32.tf32.f32 "
        "{%0,%1,%2,%3}, {%4,%5,%6,%7}, {%8,%9}, {%10,%11,%12,%13};"
        : "=f"(d[0]), "=f"(d[1]), "=f"(d[2]), "=f"(d[3])
        : "r"(a[0]), "r"(a[1]), "r"(a[2]), "r"(a[3]),
          "r"(b[0]), "r"(b[1]),
          "f"(c[0]), "f"(c[1]), "f"(c[2]), "f"(c[3]));
}

// ---- GEMM: C[M x 256] = concat-A[M x KTOT] @ W[KTOT x 256] (+epilogue) ----
// A0 covers k in [0,256); A1 covers k in [256,512) when KTOT=512.
// TF32 tensor cores, 128x128 tile, 8 warps (64x32 each), double-buffered smem.
template <int MODE, int KTOT>
__global__ __launch_bounds__(256, 2)
void gemm_tc(const float* __restrict__ A0, const float* __restrict__ A1,
             const float* __restrict__ W, float* __restrict__ Cout,
             const float* __restrict__ bias, const float* __restrict__ res,
             int M)
{
    __shared__ unsigned As[2][128][20];   // [row][k], pad -> conflict-free
    __shared__ unsigned Bs[2][16][136];   // [k][n],  pad -> conflict-free

    const int tid  = threadIdx.x;
    const int wid  = tid >> 5;
    const int lane = tid & 31;
    const int g = lane >> 2;
    const int c = lane & 3;

    const int rowBase = blockIdx.y * 128;
    const int colBase = blockIdx.x * 128;
    const int wr = (wid & 1) * 64;
    const int wc = (wid >> 1) * 32;

    float acc[4][4][4];
#pragma unroll
    for (int i = 0; i < 4; i++)
#pragma unroll
        for (int j = 0; j < 4; j++)
#pragma unroll
            for (int k = 0; k < 4; k++) acc[i][j][k] = 0.f;

    float4 pa[2], pb[2];

    // prefetch helpers (load slab k0 into registers)
    auto loadSlab = [&](int k0) {
        const float* Asrc = (KTOT == 512 && k0 >= 256) ? A1 : A0;
        const int kb = k0 & 255;
#pragma unroll
        for (int i = 0; i < 2; i++) {
            const int s = tid + i * 256;
            const int r = s >> 2, kk = (s & 3) * 4;
            const int gr = rowBase + r;
            pa[i] = (gr < M)
                ? *reinterpret_cast<const float4*>(&Asrc[(size_t)gr * D + kb + kk])
                : make_float4(0.f, 0.f, 0.f, 0.f);
        }
#pragma unroll
        for (int i = 0; i < 2; i++) {
            const int s = tid + i * 256;
            const int kk2 = s >> 5, n4 = (s & 31) * 4;
            pb[i] = *reinterpret_cast<const float4*>(&W[(size_t)(k0 + kk2) * D + colBase + n4]);
        }
    };

    loadSlab(0);
    int bufId = 0;

    for (int k0 = 0; k0 < KTOT; k0 += 16) {
        // store prefetched slab into smem (convert to tf32)
#pragma unroll
        for (int i = 0; i < 2; i++) {
            const int s = tid + i * 256;
            const int r = s >> 2, kk = (s & 3) * 4;
            As[bufId][r][kk + 0] = f2tf(pa[i].x);
            As[bufId][r][kk + 1] = f2tf(pa[i].y);
            As[bufId][r][kk + 2] = f2tf(pa[i].z);
            As[bufId][r][kk + 3] = f2tf(pa[i].w);
        }
#pragma unroll
        for (int i = 0; i < 2; i++) {
            const int s = tid + i * 256;
            const int kk2 = s >> 5, n4 = (s & 31) * 4;
            Bs[bufId][kk2][n4 + 0] = f2tf(pb[i].x);
            Bs[bufId][kk2][n4 + 1] = f2tf(pb[i].y);
            Bs[bufId][kk2][n4 + 2] = f2tf(pb[i].z);
            Bs[bufId][kk2][n4 + 3] = f2tf(pb[i].w);
        }
        __syncthreads();

        if (k0 + 16 < KTOT) loadSlab(k0 + 16);  // overlap LDG with HMMA

#pragma unroll
        for (int ks = 0; ks < 16; ks += 8) {
            unsigned a[4][4], b[4][2];
#pragma unroll
            for (int mf = 0; mf < 4; mf++) {
                const int mrow = wr + mf * 16;
                a[mf][0] = As[bufId][mrow + g    ][ks + c    ];
                a[mf][1] = As[bufId][mrow + g + 8][ks + c    ];
                a[mf][2] = As[bufId][mrow + g    ][ks + c + 4];
                a[mf][3] = As[bufId][mrow + g + 8][ks + c + 4];
            }
#pragma unroll
            for (int nf = 0; nf < 4; nf++) {
                const int ncol = wc + nf * 8;
                b[nf][0] = Bs[bufId][ks + c    ][ncol + g];
                b[nf][1] = Bs[bufId][ks + c + 4][ncol + g];
            }
#pragma unroll
            for (int mf = 0; mf < 4; mf++)
#pragma unroll
                for (int nf = 0; nf < 4; nf++)
                    mma_tf32(acc[mf][nf], a[mf], b[nf], acc[mf][nf]);
        }
        bufId ^= 1;
    }

#pragma unroll
    for (int mf = 0; mf < 4; mf++) {
#pragma unroll
        for (int half = 0; half < 2; half++) {
            const int r = rowBase + wr + mf * 16 + g + half * 8;
            if (r >= M) continue;
#pragma unroll
            for (int nf = 0; nf < 4; nf++) {
                const int col = colBase + wc + nf * 8 + 2 * c;
                float2 v = make_float2(acc[mf][nf][half * 2], acc[mf][nf][half * 2 + 1]);
                if (MODE == EP_BIAS) {
                    v.x += bias[col + 0];
                    v.y += bias[col + 1];
                } else if (MODE == EP_RELU_BIAS || MODE == EP_RELU_BIAS_RES) {
                    v.x = fmaxf(v.x + bias[col + 0], 0.f);
                    v.y = fmaxf(v.y + bias[col + 1], 0.f);
                    if (MODE == EP_RELU_BIAS_RES) {
                        const float2 rr = *reinterpret_cast<const float2*>(&res[(size_t)r * D + col]);
                        v.x += rr.x; v.y += rr.y;
                    }
                }
                *reinterpret_cast<float2*>(&Cout[(size_t)r * D + col]) = v;
            }
        }
    }
}

// ---------------- CSR build --------------------------------------------------
__global__ __launch_bounds__(256)
void hist_kernel(const int* __restrict__ src, const int* __restrict__ dst,
                 int* cntF, int* cntV)
{
    const int e = blockIdx.x * 256 + threadIdx.x;
    if (e >= EE) return;
    atomicAdd(&cntF[__ldg(&dst[e])], 1);
    atomicAdd(&cntV[__ldg(&src[e])], 1);
}

__global__ __launch_bounds__(1024)
void scan_excl(const int* __restrict__ cnt, int* __restrict__ off,
               int* __restrict__ cur, int n)
{
    __shared__ int wsum[32];
    __shared__ int carry;
    const int t = threadIdx.x, lane = t & 31, w = t >> 5;
    if (t == 0) carry = 0;
    __syncthreads();
    for (int base = 0; base < n; base += 1024) {
        const int i = base + t;
        const int x = (i < n) ? cnt[i] : 0;
        int incl = x;
#pragma unroll
        for (int o = 1; o < 32; o <<= 1) {
            const int v = __shfl_up_sync(0xffffffffu, incl, o);
            if (lane >= o) incl += v;
        }
        if (lane == 31) wsum[w] = incl;
        __syncthreads();
        if (w == 0) {
            const int s = wsum[lane];
            int si = s;
#pragma unroll
            for (int o = 1; o < 32; o <<= 1) {
                const int v = __shfl_up_sync(0xffffffffu, si, o);
                if (lane >= o) si += v;
            }
            wsum[lane] = si - s;  // exclusive warp offsets
        }
        __syncthreads();
        const int ex = carry + wsum[w] + incl - x;
        if (i < n) { off[i] = ex; cur[i] = ex; }
        __syncthreads();
        if (t == 1023) carry += wsum[31] + incl;
        __syncthreads();
    }
    if (t == 0) off[n] = carry;
}

__global__ __launch_bounds__(256)
void scatter_kernel(const int* __restrict__ src, const int* __restrict__ dst,
                    int* curF, int* curV, int* elF, int* elV)
{
    const int e = blockIdx.x * 256 + threadIdx.x;
    if (e >= EE) return;
    const int s = __ldg(&src[e]);
    const int d2 = __ldg(&dst[e]);
    elF[atomicAdd(&curF[d2], 1)] = s;
    elV[atomicAdd(&curV[s], 1)] = d2;
}

// ---------------- CSR gather-aggregate --------------------------------------
// out[row] = sum_{o in nbrs(row)} relu(Hself[row] + Hother[o])   (bias in Hself)
__global__ __launch_bounds__(256)
void aggregate(const float* __restrict__ Hself, const float* __restrict__ Hother,
               const int* __restrict__ off, const int* __restrict__ elist,
               float* __restrict__ out, int n)
{
    const int row = blockIdx.x * 4 + threadIdx.y;
    if (row >= n) return;
    const int d = threadIdx.x * 4;
    const float4 b = *reinterpret_cast<const float4*>(&Hself[(size_t)row * D + d]);
    float4 acc = make_float4(0.f, 0.f, 0.f, 0.f);
    int j = __ldg(&off[row]);
    const int e = __ldg(&off[row + 1]);
    for (; j + 2 <= e; j += 2) {
        const int o0 = __ldg(&elist[j]);
        const int o1 = __ldg(&elist[j + 1]);
        const float4 v0 = *reinterpret_cast<const float4*>(&Hother[(size_t)o0 * D + d]);
        const float4 v1 = *reinterpret_cast<const float4*>(&Hother[(size_t)o1 * D + d]);
        acc.x += fmaxf(b.x + v0.x, 0.f) + fmaxf(b.x + v1.x, 0.f);
        acc.y += fmaxf(b.y + v0.y, 0.f) + fmaxf(b.y + v1.y, 0.f);
        acc.z += fmaxf(b.z + v0.z, 0.f) + fmaxf(b.z + v1.z, 0.f);
        acc.w += fmaxf(b.w + v0.w, 0.f) + fmaxf(b.w + v1.w, 0.f);
    }
    if (j < e) {
        const int o0 = __ldg(&elist[j]);
        const float4 v0 = *reinterpret_cast<const float4*>(&Hother[(size_t)o0 * D + d]);
        acc.x += fmaxf(b.x + v0.x, 0.f);
        acc.y += fmaxf(b.y + v0.y, 0.f);
        acc.z += fmaxf(b.z + v0.z, 0.f);
        acc.w += fmaxf(b.w + v0.w, 0.f);
    }
    *reinterpret_cast<float4*>(&out[(size_t)row * D + d]) = acc;
}

// ---------------- attention pooling -----------------------------------------
__global__ __launch_bounds__(256)
void gate_kernel(const float* __restrict__ F, const float* __restrict__ gW,
                 const float* __restrict__ gb, float* __restrict__ gate)
{
    const int w = threadIdx.x >> 5, lane = threadIdx.x & 31;
    const int row = blockIdx.x * 8 + w;
    if (row >= NF) return;
    float s = 0.f;
#pragma unroll
    for (int i = 0; i < 8; i++) {
        const int k = lane + i * 32;
        s += F[(size_t)row * D + k] * __ldg(&gW[k]);
    }
#pragma unroll
    for (int o = 16; o > 0; o >>= 1) s += __shfl_xor_sync(0xffffffff, s, o);
    if (lane == 0) gate[row] = s + gb[0];
}

__device__ __forceinline__ int lbound(const int* __restrict__ a, int n, int v)
{
    int lo = 0, hi = n;
    while (lo < hi) {
        const int mid = (lo + hi) >> 1;
        if (a[mid] < v) lo = mid + 1; else hi = mid;
    }
    return lo;
}

__global__ __launch_bounds__(256)
void graph_agg(const float* __restrict__ gate, const float* __restrict__ T,
               const int* __restrict__ batch, float* __restrict__ gagg)
{
    __shared__ float red[256];
    __shared__ int sse[2];
    const int g = blockIdx.x, tid = threadIdx.x;
    if (tid == 0) sse[0] = lbound(batch, NF, g);
    if (tid == 1) sse[1] = lbound(batch, NF, g + 1);
    __syncthreads();
    const int s = sse[0], e = sse[1];

    float m = -INFINITY;
    for (int i = s + tid; i < e; i += 256) m = fmaxf(m, __ldg(&gate[i]));
    red[tid] = m; __syncthreads();
    for (int o = 128; o > 0; o >>= 1) {
        if (tid < o) red[tid] = fmaxf(red[tid], red[tid + o]);
        __syncthreads();
    }
    const float mm = red[0]; __syncthreads();

    float sum = 0.f;
    for (int i = s + tid; i < e; i += 256) sum += expf(__ldg(&gate[i]) - mm);
    red[tid] = sum; __syncthreads();
    for (int o = 128; o > 0; o >>= 1) {
        if (tid < o) red[tid] += red[tid + o];
        __syncthreads();
    }
    const float inv = (e > s) ? 1.f / red[0] : 0.f;

    float acc = 0.f;
    for (int i = s; i < e; i++) {
        const float alpha = expf(__ldg(&gate[i]) - mm) * inv;
        acc += alpha * T[(size_t)i * D + tid];
    }
    gagg[g * D + tid] = acc;
}

__global__ __launch_bounds__(256)
void final_g(const float* __restrict__ gagg, const float* __restrict__ glW,
             const float* __restrict__ glb, float* __restrict__ out)
{
    __shared__ float row[D];
    const int g = blockIdx.x, c = threadIdx.x;
    row[c] = gagg[g * D + c];
    __syncthreads();
    float s = glb[c];
#pragma unroll 8
    for (int k = 0; k < D; k++) s += row[k] * glW[(size_t)k * D + c];
    out[(size_t)g * D + c] = fmaxf(s, 0.f);
}

// ---------------------------------------------------------------------------
extern "C" void kernel_launch(void* const* d_in, const int* in_sizes, int n_in,
                              void* d_out, int out_size)
{
    const float* variables = (const float*)d_in[0];
    const float* factors   = (const float*)d_in[1];
    // d_in[2] = edge_attr (unused by the math)
    const int* edge_index  = (const int*)d_in[3];
    const int* batch       = (const int*)d_in[4];
    const float* mW_v2f = (const float*)d_in[5];
    const float* mb_v2f = (const float*)d_in[6];
    const float* cW_v2f = (const float*)d_in[7];
    const float* cb_v2f = (const float*)d_in[8];
    const float* mW_f2v = (const float*)d_in[9];
    const float* mb_f2v = (const float*)d_in[10];
    const float* cW_f2v = (const float*)d_in[11];
    const float* cb_f2v = (const float*)d_in[12];
    const float* gate_W = (const float*)d_in[13];
    const float* gate_b = (const float*)d_in[14];
    const float* att_W  = (const float*)d_in[15];
    const float* att_b  = (const float*)d_in[16];
    const float* gl_W   = (const float*)d_in[17];
    const float* gl_b   = (const float*)d_in[18];

    const int* src = edge_index;        // row 0: variable idx
    const int* dst = edge_index + EE;   // row 1: factor idx

    float* outV = (float*)d_out;
    float* outF = outV + (size_t)NV * D;
    float* outG = outF + (size_t)NF * D;

    float *bufF1, *bufF2, *bufV1, *bufV2, *gate, *gagg;
    int *cntF, *cntV, *offF, *offV, *curF, *curV, *elF, *elV;
    cudaGetSymbolAddress((void**)&bufF1, g_bufF1);
    cudaGetSymbolAddress((void**)&bufF2, g_bufF2);
    cudaGetSymbolAddress((void**)&bufV1, g_bufV1);
    cudaGetSymbolAddress((void**)&bufV2, g_bufV2);
    cudaGetSymbolAddress((void**)&gate,  g_gate);
    cudaGetSymbolAddress((void**)&gagg,  g_gagg);
    cudaGetSymbolAddress((void**)&cntF, g_cntF);
    cudaGetSymbolAddress((void**)&cntV, g_cntV);
    cudaGetSymbolAddress((void**)&offF, g_offF);
    cudaGetSymbolAddress((void**)&offV, g_offV);
    cudaGetSymbolAddress((void**)&curF, g_curF);
    cudaGetSymbolAddress((void**)&curV, g_curV);
    cudaGetSymbolAddress((void**)&elF,  g_elF);
    cudaGetSymbolAddress((void**)&elV,  g_elV);

    // ---- CSR build (once per launch) ----
    cudaMemsetAsync(cntF, 0, NF * sizeof(int), 0);
    cudaMemsetAsync(cntV, 0, NV * sizeof(int), 0);
    const int eb = (EE + 255) / 256;
    hist_kernel<<<eb, 256>>>(src, dst, cntF, cntV);
    scan_excl<<<1, 1024>>>(cntF, offF, curF, NF);
    scan_excl<<<1, 1024>>>(cntV, offV, curV, NV);
    scatter_kernel<<<eb, 256>>>(src, dst, curF, curV, elF, elV);

    // working copies live directly in d_out
    cudaMemcpyAsync(outV, variables, (size_t)NV * D * sizeof(float),
                    cudaMemcpyDeviceToDevice, 0);
    cudaMemcpyAsync(outF, factors, (size_t)NF * D * sizeof(float),
                    cudaMemcpyDeviceToDevice, 0);

    const dim3 gemmBlk(256);
    const dim3 gridF(2, (NF + 127) / 128);
    const dim3 gridV(2, (NV + 127) / 128);
    const dim3 aggBlk(64, 4);

    // factor/variable buffer ping-pong across layers:
    float* Fcur = outF;  float* Vcur = outV;
    float* Fnxt = bufF1; float* Vnxt = bufV1;

    for (int l = 0; l < 2; l++) {
        const float* FhBuf = (l == 0) ? bufF1 : outF;   // scratch for Fh (dead old data)
        const float* VhBuf = (l == 0) ? bufV1 : outV;

        // ---- variable -> factor ----
        {
            const float* mW = mW_v2f + (size_t)l * D2 * D;
            const float* mb = mb_v2f + (size_t)l * D;
            const float* cW = cW_v2f + (size_t)l * D2 * D;
            const float* cb = cb_v2f + (size_t)l * D;
            float* Fh = (float*)FhBuf;
            float* Vh = (l == 0) ? bufV1 : bufV2;

            gemm_tc<EP_BIAS, 256><<<gridF, gemmBlk>>>(Fcur, nullptr, mW,         Fh, mb, nullptr, NF);
            gemm_tc<EP_NONE, 256><<<gridV, gemmBlk>>>(Vcur, nullptr, mW + D * D, Vh, nullptr, nullptr, NV);
            aggregate<<<(NF + 3) / 4, aggBlk>>>(Fh, Vh, offF, elF, bufF2, NF);
            gemm_tc<EP_RELU_BIAS, 512><<<gridF, gemmBlk>>>(Fcur, bufF2, cW, Fnxt, cb, nullptr, NF);
            Fcur = Fnxt; Fnxt = (Fcur == outF) ? bufF1 : outF;
        }
        // ---- factor -> variable ----
        {
            const float* mW = mW_f2v + (size_t)l * D2 * D;
            const float* mb = mb_f2v + (size_t)l * D;
            const float* cW = cW_f2v + (size_t)l * D2 * D;
            const float* cb = cb_f2v + (size_t)l * D;
            float* Vh = (float*)VhBuf;
            float* Fh2 = bufF2;   // aggr from v2f is consumed; reuse

            gemm_tc<EP_BIAS, 256><<<gridV, gemmBlk>>>(Vcur, nullptr, mW,         Vh, mb, nullptr, NV);
            gemm_tc<EP_NONE, 256><<<gridF, gemmBlk>>>(Fcur, nullptr, mW + D * D, Fh2, nullptr, nullptr, NF);
            aggregate<<<(NV + 3) / 4, aggBlk>>>(Vh, Fh2, offV, elV, bufV2, NV);
            gemm_tc<EP_RELU_BIAS_RES, 512><<<gridV, gemmBlk>>>(Vcur, bufV2, cW, Vnxt, cb, Vcur, NV);
            Vcur = Vnxt; Vnxt = (Vcur == outV) ? bufV1 : outV;
        }
    }
    // after 2 layers: Fcur == outF, Vcur == outV (ping-pong returns)

    // ---- GlobalNode attention pooling ----
    gate_kernel<<<(NF + 7) / 8, 256>>>(outF, gate_W, gate_b, gate);
    gemm_tc<EP_BIAS, 256><<<gridF, gemmBlk>>>(outF, nullptr, att_W, bufF1, att_b, nullptr, NF);
    graph_agg<<<GG, 256>>>(gate, bufF1, batch, gagg);
    final_g<<<GG, 256>>>(gagg, gl_W, gl_b, outG);
}